// round 15
// baseline (speedup 1.0000x reference)
#include <cuda_runtime.h>
#include <cuda_fp16.h>
#include <cstdint>
#include <math.h>

#define MAXN 100000
#define MAXE 600000

// ---------------- scratch (no allocations allowed) ----------------
__device__ __align__(16) float  g_hcat[(size_t)MAXN * 512];   // fp32 h0|h1|h2|h3 per node
__device__ __align__(16) __half g_hh  [(size_t)MAXN * 512];   // fp16 mirror (GEMM A operand)
__device__ __align__(16) __half g_z16 [(size_t)MAXN * 128];
__device__ __align__(16) __half g_t16 [(size_t)MAXN * 256];
__device__ __align__(16) __half g_o16 [(size_t)MAXN * 128];
__device__ int    g_deg   [MAXN];
__device__ int    g_rowptr[MAXN + 1];
__device__ int    g_cursor[MAXN];
__device__ int    g_bsum  [256];
__device__ int    g_boff  [256];
__device__ int    g_srcs  [MAXE];
__device__ __align__(16) float g_sattr[MAXN * 4];
__device__ float  g_gsum  [64 * 128];
__device__ float  g_cnt   [64];
__device__ __align__(16) __half g_wth[278528];
__device__ __align__(16) __half g_wtl[278528];

// ---------------- fused init: weight prep + zeroing + input projection ----------------
__global__ void k_init(const float* __restrict__ x, const float* __restrict__ W,
                       const float* __restrict__ b,
                       const float* __restrict__ W1, const float* __restrict__ W2,
                       const float* __restrict__ O1, const float* __restrict__ O2,
                       int n, int nb) {
    int tid = threadIdx.x;
    int idx = blockIdx.x * 256 + tid;
    // zero
    if (idx < n) g_deg[idx] = 0;
    if (idx < n * 4) g_sattr[idx] = 0.f;
    if (idx < nb * 128) g_gsum[idx] = 0.f;
    if (idx < nb) g_cnt[idx] = 0.f;
    // weight prep (transpose + fp16 hi/lo split)
    if (idx < 278528) {
        const float* src; int K, N, base, rel;
        if (idx < 98304)       { int l = idx / 32768; rel = idx % 32768; src = W1 + (size_t)l * 32768; K = 128; N = 256; base = l * 32768; }
        else if (idx < 196608) { int j = idx - 98304; int l = j / 32768; rel = j % 32768; src = W2 + (size_t)l * 32768; K = 256; N = 128; base = 98304 + l * 32768; }
        else if (idx < 262144) { rel = idx - 196608; src = O1; K = 512; N = 128; base = 196608; }
        else                   { rel = idx - 262144; src = O2; K = 128; N = 128; base = 262144; }
        int k = rel / N, nn = rel % N;
        float v = src[rel];
        __half h = __float2half_rn(v);
        __half l2 = __float2half_rn(v - __half2float(h));
        g_wth[base + nn * K + k] = h;
        g_wtl[base + nn * K + k] = l2;
    }
    // input projection: 2 nodes per block
    int node = blockIdx.x * 2 + (tid >> 7);
    int c = tid & 127;
    __shared__ float xs[2][12];
    if (c < 12 && node < n) xs[tid >> 7][c] = x[node * 12 + c];
    __syncthreads();
    if (node < n) {
        float a = b[c];
#pragma unroll
        for (int k = 0; k < 12; k++) a += xs[tid >> 7][k] * W[k * 128 + c];
        g_hcat[(size_t)node * 512 + c] = a;
        g_hh[(size_t)node * 512 + c] = __float2half_rn(a);
    }
}

// ---------------- CSR build ----------------
__global__ void k_count(const int* __restrict__ dst, const float* __restrict__ ea, int e) {
    int i = blockIdx.x * blockDim.x + threadIdx.x;
    if (i >= e) return;
    int d = dst[i];
    atomicAdd(&g_deg[d], 1);
    atomicAdd(&g_sattr[d * 4 + 0], ea[3 * i]);
    atomicAdd(&g_sattr[d * 4 + 1], ea[3 * i + 1]);
    atomicAdd(&g_sattr[d * 4 + 2], ea[3 * i + 2]);
}
__global__ void k_scan1(int n) {
    int t = threadIdx.x, b = blockIdx.x;
    int i = b * 512 + t;
    int v = (i < n) ? g_deg[i] : 0;
    int lane = t & 31, w = t >> 5;
    int x = v;
#pragma unroll
    for (int o = 1; o < 32; o <<= 1) {
        int y = __shfl_up_sync(0xFFFFFFFFu, x, o);
        if (lane >= o) x += y;
    }
    __shared__ int ws[16];
    if (lane == 31) ws[w] = x;
    __syncthreads();
    if (w == 0) {
        int y = (lane < 16) ? ws[lane] : 0;
#pragma unroll
        for (int o = 1; o < 16; o <<= 1) {
            int z = __shfl_up_sync(0xFFFFFFFFu, y, o);
            if (lane >= o) y += z;
        }
        if (lane < 16) ws[lane] = y;
    }
    __syncthreads();
    int incl = x + (w > 0 ? ws[w - 1] : 0);
    if (i < n) g_rowptr[i] = incl - v;
    if (t == 511) g_bsum[b] = incl;
}
__global__ void k_scan2(int nb) {
    __shared__ int s[256];
    int t = threadIdx.x;
    s[t] = (t < nb) ? g_bsum[t] : 0;
    __syncthreads();
    for (int o = 1; o < 256; o <<= 1) {
        int v = (t >= o) ? s[t - o] : 0;
        __syncthreads();
        s[t] += v;
        __syncthreads();
    }
    g_boff[t] = (t == 0) ? 0 : s[t - 1];
}
__global__ void k_scan3(int n, int e) {
    int i = blockIdx.x * blockDim.x + threadIdx.x;
    if (i < n) {
        int r = g_rowptr[i] + g_boff[i >> 9];
        g_rowptr[i] = r;
        g_cursor[i] = r;
    }
    if (i == 0) g_rowptr[n] = e;
}
__global__ void k_scatter(const int* __restrict__ src, const int* __restrict__ dst, int e) {
    int i = blockIdx.x * blockDim.x + threadIdx.x;
    if (i >= e) return;
    int p = atomicAdd(&g_cursor[dst[i]], 1);
    g_srcs[p] = src[i];
}

// ---------------- aggregation ----------------
__global__ void k_aggregate(const float* __restrict__ edgeW, const float* __restrict__ edgeb,
                            const float* __restrict__ eps, int l, int n) {
    int gid = blockIdx.x * blockDim.x + threadIdx.x;
    int node = gid >> 5, lane = gid & 31;
    if (node >= n) return;
    int c = lane * 4;
    float4 w0 = *(const float4*)(edgeW + c);
    float4 w1 = *(const float4*)(edgeW + 128 + c);
    float4 w2 = *(const float4*)(edgeW + 256 + c);
    float4 eb = *(const float4*)(edgeb + c);
    float ep = 1.f + eps[l];
    const float* hb = g_hcat + (size_t)l * 128;
    float4 hh = *(const float4*)(hb + (size_t)node * 512 + c);
    float4 sa = *(const float4*)(g_sattr + node * 4);
    int j0 = g_rowptr[node], j1 = g_rowptr[node + 1];
    float dg = (float)(j1 - j0);
    float4 acc;
    acc.x = ep * hh.x + sa.x * w0.x + sa.y * w1.x + sa.z * w2.x + dg * eb.x;
    acc.y = ep * hh.y + sa.x * w0.y + sa.y * w1.y + sa.z * w2.y + dg * eb.y;
    acc.z = ep * hh.z + sa.x * w0.z + sa.y * w1.z + sa.z * w2.z + dg * eb.z;
    acc.w = ep * hh.w + sa.x * w0.w + sa.y * w1.w + sa.z * w2.w + dg * eb.w;
    for (int j = j0; j < j1; j++) {
        int s = g_srcs[j];
        float4 hs = *(const float4*)(hb + (size_t)s * 512 + c);
        acc.x += hs.x; acc.y += hs.y; acc.z += hs.z; acc.w += hs.w;
    }
    __half2 h0 = __floats2half2_rn(acc.x, acc.y);
    __half2 h1 = __floats2half2_rn(acc.z, acc.w);
    uint2 o; o.x = *(uint32_t*)&h0; o.y = *(uint32_t*)&h1;
    *(uint2*)(g_z16 + (size_t)node * 128 + c) = o;
}

// ---------------- tensor-core GEMM (fp16 A + split-B, 2-stage cp.async) ----------------
__device__ __forceinline__ void mma16816(float* c, const unsigned* a, const unsigned* b) {
    asm volatile(
        "mma.sync.aligned.m16n8k16.row.col.f32.f16.f16.f32 "
        "{%0,%1,%2,%3}, {%4,%5,%6,%7}, {%8,%9}, {%0,%1,%2,%3};\n"
        : "+f"(c[0]), "+f"(c[1]), "+f"(c[2]), "+f"(c[3])
        : "r"(a[0]), "r"(a[1]), "r"(a[2]), "r"(a[3]), "r"(b[0]), "r"(b[1]));
}
__device__ __forceinline__ void ldm_x4(unsigned* r, uint32_t a) {
    asm volatile("ldmatrix.sync.aligned.m8n8.x4.shared.b16 {%0,%1,%2,%3}, [%4];"
        : "=r"(r[0]), "=r"(r[1]), "=r"(r[2]), "=r"(r[3]) : "r"(a));
}
__device__ __forceinline__ uint32_t smem_u32(const void* p) {
    uint32_t a;
    asm("{ .reg .u64 t; cvta.to.shared.u64 t, %1; cvt.u32.u64 %0, t; }" : "=r"(a) : "l"(p));
    return a;
}
__device__ __forceinline__ void cpa16(uint32_t s, const void* g) {
    asm volatile("cp.async.cg.shared.global [%0], [%1], 16;" :: "r"(s), "l"(g));
}
#define CPA_COMMIT() asm volatile("cp.async.commit_group;" ::: "memory")
#define CPA_WAIT0()  asm volatile("cp.async.wait_group 0;" ::: "memory")

#define SMS 40
#define BUFB 10240u
#define OF_A(s)  ((s) * BUFB)
#define OF_BH(s) (2u * BUFB + (s) * BUFB)
#define OF_BL(s) (4u * BUFB + (s) * BUFB)
#define OF_RED   (6u * BUFB)
#define SMEM_MMA (6 * 10240 + 2048)   // 63488

// EPI: 0=+bias, 1=relu(+bias), 2=relu(BN(+bias)), 3=relu(BN(+bias))+Res+LN (grid.x==1)
template<int EPI, bool O16>
__global__ __launch_bounds__(256, 2) void k_mma(
    const __half* __restrict__ A, int lda,
    const __half* __restrict__ Wh, const __half* __restrict__ Wl, int K,
    float* __restrict__ C, __half* __restrict__ C16, int ldc, int M,
    const float* __restrict__ bias,
    const float* __restrict__ bng, const float* __restrict__ bnb,
    const float* __restrict__ bnrm, const float* __restrict__ bnrv,
    const float* __restrict__ Res, int ldr,
    const float* __restrict__ lng, const float* __restrict__ lnb) {
    extern __shared__ __align__(16) char smx[];
    uint32_t smb = smem_u32(smx);
    float* sRedP = (float*)(smx + OF_RED);

    int tid = threadIdx.x, lane = tid & 31, wid = tid >> 5;
    int wy = wid & 3, wx = wid >> 2;
    int mW = wy * 32, nW = wx * 64;
    int g = lane >> 2, qt = lane & 3;
    int rowBase = blockIdx.y * 128, colBase = blockIdx.x * 128;

    float c[2][8][4];
#pragma unroll
    for (int i = 0; i < 2; i++)
#pragma unroll
        for (int j = 0; j < 8; j++)
#pragma unroll
            for (int m = 0; m < 4; m++) c[i][j][m] = 0.f;

    uint32_t aOff = (uint32_t)((mW + (lane & 15)) * SMS + ((lane >> 4) << 3)) * 2;
    uint32_t bOff = (uint32_t)((nW + ((lane >> 4) << 3) + (lane & 7)) * SMS + (((lane >> 3) & 1) << 3)) * 2;

    uint32_t tSm[2];
    size_t aGm[2], bGm[2];
#pragma unroll
    for (int i = 0; i < 2; i++) {
        int v = tid + i * 256;
        int r = v >> 2, kc8 = (v & 3) * 8;
        tSm[i] = (uint32_t)(r * SMS + kc8) * 2;
        int ar = rowBase + r; if (ar >= M) ar = M - 1;
        aGm[i] = (size_t)ar * lda + kc8;
        bGm[i] = (size_t)(colBase + r) * K + kc8;
    }

    // prologue: tile 0
#pragma unroll
    for (int i = 0; i < 2; i++) {
        cpa16(smb + OF_A(0)  + tSm[i], A  + aGm[i]);
        cpa16(smb + OF_BH(0) + tSm[i], Wh + bGm[i]);
        cpa16(smb + OF_BL(0) + tSm[i], Wl + bGm[i]);
    }
    CPA_COMMIT();

    int nk = K >> 5;
    for (int t = 0; t < nk; t++) {
        int cur = t & 1, nxt = cur ^ 1;
        CPA_WAIT0();
        __syncthreads();
        if (t + 1 < nk) {
            int k0 = (t + 1) << 5;
#pragma unroll
            for (int i = 0; i < 2; i++) {
                cpa16(smb + OF_A(nxt)  + tSm[i], A  + aGm[i] + k0);
                cpa16(smb + OF_BH(nxt) + tSm[i], Wh + bGm[i] + k0);
                cpa16(smb + OF_BL(nxt) + tSm[i], Wl + bGm[i] + k0);
            }
            CPA_COMMIT();
        }
        uint32_t aB  = smb + OF_A(cur)  + aOff;
        uint32_t bhB = smb + OF_BH(cur) + bOff;
        uint32_t blB = smb + OF_BL(cur) + bOff;
#pragma unroll
        for (int kc = 0; kc < 2; kc++) {
            uint32_t kByte = (uint32_t)(kc * 16) * 2;
            unsigned ah[2][4], bh[8][2], bl[8][2];
#pragma unroll
            for (int i = 0; i < 2; i++)
                ldm_x4(ah[i], aB + (uint32_t)(i * 16 * SMS) * 2 + kByte);
#pragma unroll
            for (int j2 = 0; j2 < 4; j2++) {
                uint32_t rb = (uint32_t)(j2 * 16 * SMS) * 2 + kByte;
                ldm_x4(&bh[j2 * 2][0], bhB + rb);
                ldm_x4(&bl[j2 * 2][0], blB + rb);
            }
#pragma unroll
            for (int i = 0; i < 2; i++)
#pragma unroll
                for (int j = 0; j < 8; j++) {
                    mma16816(c[i][j], ah[i], bh[j]);
                    mma16816(c[i][j], ah[i], bl[j]);
                }
        }
    }

    if (EPI == 3) {
        __syncthreads();   // protect sRed reuse (only EPI3 touches smem after loop)
        float cs[8][2], ct[8][2];
#pragma unroll
        for (int j = 0; j < 8; j++) {
#pragma unroll
            for (int h = 0; h < 2; h++) {
                int col = colBase + nW + j * 8 + qt * 2 + h;
                float s = bng[col] * rsqrtf(bnrv[col] + 1e-5f);
                cs[j][h] = s; ct[j][h] = bnb[col] + (bias[col] - bnrm[col]) * s;
            }
        }
        float s[2][2], q[2][2];
#pragma unroll
        for (int i = 0; i < 2; i++) { s[i][0] = s[i][1] = 0.f; q[i][0] = q[i][1] = 0.f; }
#pragma unroll
        for (int i = 0; i < 2; i++) {
            int r1 = rowBase + mW + i * 16 + g, r2 = r1 + 8;
#pragma unroll
            for (int j = 0; j < 8; j++) {
                int colL = nW + j * 8 + qt * 2;
                float2 res1 = make_float2(0.f, 0.f), res2 = make_float2(0.f, 0.f);
                if (r1 < M) res1 = *(const float2*)(Res + (size_t)r1 * ldr + colL);
                if (r2 < M) res2 = *(const float2*)(Res + (size_t)r2 * ldr + colL);
                float v0 = fmaxf(c[i][j][0] * cs[j][0] + ct[j][0], 0.f) + res1.x;
                float v1 = fmaxf(c[i][j][1] * cs[j][1] + ct[j][1], 0.f) + res1.y;
                float v2 = fmaxf(c[i][j][2] * cs[j][0] + ct[j][0], 0.f) + res2.x;
                float v3 = fmaxf(c[i][j][3] * cs[j][1] + ct[j][1], 0.f) + res2.y;
                c[i][j][0] = v0; c[i][j][1] = v1; c[i][j][2] = v2; c[i][j][3] = v3;
                s[i][0] += v0 + v1; q[i][0] += v0 * v0 + v1 * v1;
                s[i][1] += v2 + v3; q[i][1] += v2 * v2 + v3 * v3;
            }
        }
#pragma unroll
        for (int i = 0; i < 2; i++)
#pragma unroll
            for (int h = 0; h < 2; h++) {
                s[i][h] += __shfl_xor_sync(0xFFFFFFFFu, s[i][h], 1);
                s[i][h] += __shfl_xor_sync(0xFFFFFFFFu, s[i][h], 2);
                q[i][h] += __shfl_xor_sync(0xFFFFFFFFu, q[i][h], 1);
                q[i][h] += __shfl_xor_sync(0xFFFFFFFFu, q[i][h], 2);
            }
        if (qt == 0) {
#pragma unroll
            for (int i = 0; i < 2; i++)
#pragma unroll
                for (int h = 0; h < 2; h++) {
                    int lr = mW + i * 16 + g + h * 8;
                    sRedP[lr * 2 + wx]       = s[i][h];
                    sRedP[256 + lr * 2 + wx] = q[i][h];
                }
        }
        __syncthreads();
#pragma unroll
        for (int i = 0; i < 2; i++)
#pragma unroll
            for (int h = 0; h < 2; h++) {
                int lr = mW + i * 16 + g + h * 8;
                int gr = rowBase + lr;
                float ts = sRedP[lr * 2] + sRedP[lr * 2 + 1];
                float tq = sRedP[256 + lr * 2] + sRedP[256 + lr * 2 + 1];
                float mu = ts * (1.f / 128.f);
                float var = tq * (1.f / 128.f) - mu * mu;
                float rr = rsqrtf(var + 1e-5f);
                if (gr < M) {
#pragma unroll
                    for (int j = 0; j < 8; j++) {
                        int colL = nW + j * 8 + qt * 2;
                        float2 o;
                        o.x = (c[i][j][h * 2]     - mu) * rr * lng[colL]     + lnb[colL];
                        o.y = (c[i][j][h * 2 + 1] - mu) * rr * lng[colL + 1] + lnb[colL + 1];
                        *(float2*)(C + (size_t)gr * ldc + colL) = o;
                        __half2 oh = __floats2half2_rn(o.x, o.y);
                        *(uint32_t*)(C16 + (size_t)gr * ldc + colL) = *(uint32_t*)&oh;
                    }
                }
            }
    } else {
        // no trailing sync needed: smem is not touched after the mainloop here
        float cs[8][2], ct[8][2];
#pragma unroll
        for (int j = 0; j < 8; j++) {
#pragma unroll
            for (int h = 0; h < 2; h++) {
                int col = colBase + nW + j * 8 + qt * 2 + h;
                if (EPI >= 2) {
                    float s = bng[col] * rsqrtf(bnrv[col] + 1e-5f);
                    cs[j][h] = s; ct[j][h] = bnb[col] + (bias[col] - bnrm[col]) * s;
                } else { ct[j][h] = bias[col]; }
            }
        }
#pragma unroll
        for (int i = 0; i < 2; i++) {
            int r1 = rowBase + mW + i * 16 + g, r2 = r1 + 8;
#pragma unroll
            for (int j = 0; j < 8; j++) {
                int col = colBase + nW + j * 8 + qt * 2;
                float o0, o1, o2, o3;
                if (EPI >= 2) {
                    o0 = c[i][j][0] * cs[j][0] + ct[j][0];
                    o1 = c[i][j][1] * cs[j][1] + ct[j][1];
                    o2 = c[i][j][2] * cs[j][0] + ct[j][0];
                    o3 = c[i][j][3] * cs[j][1] + ct[j][1];
                } else {
                    o0 = c[i][j][0] + ct[j][0];
                    o1 = c[i][j][1] + ct[j][1];
                    o2 = c[i][j][2] + ct[j][0];
                    o3 = c[i][j][3] + ct[j][1];
                }
                if (EPI >= 1) {
                    o0 = fmaxf(o0, 0.f); o1 = fmaxf(o1, 0.f);
                    o2 = fmaxf(o2, 0.f); o3 = fmaxf(o3, 0.f);
                }
                if (O16) {
                    if (r1 < M) { __half2 oh = __floats2half2_rn(o0, o1);
                        *(uint32_t*)(C16 + (size_t)r1 * ldc + col) = *(uint32_t*)&oh; }
                    if (r2 < M) { __half2 oh = __floats2half2_rn(o2, o3);
                        *(uint32_t*)(C16 + (size_t)r2 * ldc + col) = *(uint32_t*)&oh; }
                } else {
                    if (r1 < M) { float2 o; o.x = o0; o.y = o1; *(float2*)(C + (size_t)r1 * ldc + col) = o; }
                    if (r2 < M) { float2 o; o.x = o2; o.y = o3; *(float2*)(C + (size_t)r2 * ldc + col) = o; }
                }
            }
        }
    }
}

// ---------------- global mean pool ----------------
__global__ void k_pool_acc(const float* __restrict__ emb, const int* __restrict__ batch, int n) {
    int c = threadIdx.x;
    int base = blockIdx.x * 128;
    float acc0 = 0.f, cnt0 = 0.f;
    int cur = -1;
#pragma unroll 2
    for (int i = 0; i < 128; i++) {
        int nd = base + i;
        if (nd >= n) break;
        int g = batch[nd];
        if (g != cur) {
            if (cur >= 0) {
                atomicAdd(&g_gsum[cur * 128 + c], acc0);
                if (c == 0) atomicAdd(&g_cnt[cur], cnt0);
            }
            cur = g; acc0 = 0.f; cnt0 = 0.f;
        }
        acc0 += emb[(size_t)nd * 128 + c];
        cnt0 += 1.f;
    }
    if (cur >= 0) {
        atomicAdd(&g_gsum[cur * 128 + c], acc0);
        if (c == 0) atomicAdd(&g_cnt[cur], cnt0);
    }
}
__global__ void k_pool_fin(float* __restrict__ out, int b) {
    int i = blockIdx.x * blockDim.x + threadIdx.x;
    if (i >= b * 128) return;
    out[i] = g_gsum[i] / fmaxf(g_cnt[i >> 7], 1.f);
}

// ---------------- launch ----------------
extern "C" void kernel_launch(void* const* d_in, const int* in_sizes, int n_in,
                              void* d_out, int out_size) {
    const float* x      = (const float*)d_in[0];
    const int*   ei     = (const int*)d_in[1];
    const float* ea     = (const float*)d_in[2];
    const int*   batch  = (const int*)d_in[3];
    const float* in_W   = (const float*)d_in[4];
    const float* in_b   = (const float*)d_in[5];
    const float* edge_W = (const float*)d_in[6];
    const float* edge_b = (const float*)d_in[7];
    const float* mlp_W1 = (const float*)d_in[8];
    const float* mlp_b1 = (const float*)d_in[9];
    const float* bn1_g  = (const float*)d_in[10];
    const float* bn1_b  = (const float*)d_in[11];
    const float* bn1_rm = (const float*)d_in[12];
    const float* bn1_rv = (const float*)d_in[13];
    const float* mlp_W2 = (const float*)d_in[14];
    const float* mlp_b2 = (const float*)d_in[15];
    const float* bn2_g  = (const float*)d_in[16];
    const float* bn2_b  = (const float*)d_in[17];
    const float* bn2_rm = (const float*)d_in[18];
    const float* bn2_rv = (const float*)d_in[19];
    const float* eps    = (const float*)d_in[20];
    const float* ln_g   = (const float*)d_in[21];
    const float* ln_b   = (const float*)d_in[22];
    const float* out_W1 = (const float*)d_in[23];
    const float* out_b1 = (const float*)d_in[24];
    const float* out_W2 = (const float*)d_in[25];
    const float* out_b2 = (const float*)d_in[26];

    int N = in_sizes[0] / 12;
    int E = in_sizes[2] / 3;
    int B = out_size / 128 - N;
    const int* src = ei;
    const int* dst = ei + E;
    float* node_emb  = (float*)d_out;
    float* graph_emb = node_emb + (size_t)N * 128;

    float *p_hcat;
    __half *p_wh, *p_wl, *p_hh, *p_z16, *p_t16, *p_o16;
    cudaGetSymbolAddress((void**)&p_hcat, g_hcat);
    cudaGetSymbolAddress((void**)&p_hh,   g_hh);
    cudaGetSymbolAddress((void**)&p_z16,  g_z16);
    cudaGetSymbolAddress((void**)&p_t16,  g_t16);
    cudaGetSymbolAddress((void**)&p_o16,  g_o16);
    cudaGetSymbolAddress((void**)&p_wh,   g_wth);
    cudaGetSymbolAddress((void**)&p_wl,   g_wtl);

    cudaFuncSetAttribute(k_mma<0, false>, cudaFuncAttributeMaxDynamicSharedMemorySize, SMEM_MMA);
    cudaFuncSetAttribute(k_mma<1, true>,  cudaFuncAttributeMaxDynamicSharedMemorySize, SMEM_MMA);
    cudaFuncSetAttribute(k_mma<2, true>,  cudaFuncAttributeMaxDynamicSharedMemorySize, SMEM_MMA);
    cudaFuncSetAttribute(k_mma<3, false>, cudaFuncAttributeMaxDynamicSharedMemorySize, SMEM_MMA);

    // fused init: prep + zero + in_proj (one launch)
    int gInit = (N + 1) / 2;
    if (gInit < 1089) gInit = 1089;
    k_init<<<gInit, 256>>>(x, in_W, in_b, mlp_W1, mlp_W2, out_W1, out_W2, N, B);

    k_count<<<(E + 255) / 256, 256>>>(dst, ea, E);
    int nb = (N + 511) / 512;
    k_scan1<<<nb, 512>>>(N);
    k_scan2<<<1, 256>>>(nb);
    k_scan3<<<(N + 255) / 256, 256>>>(N, E);
    k_scatter<<<(E + 255) / 256, 256>>>(src, dst, E);

    int gridM = (N + 127) / 128;
    for (int l = 0; l < 3; l++) {
        k_aggregate<<<(N * 32 + 255) / 256, 256>>>(edge_W + l * 384, edge_b + l * 128, eps, l, N);
        dim3 g1(2, gridM);
        k_mma<2, true><<<g1, 256, SMEM_MMA>>>(p_z16, 128, p_wh + l * 32768, p_wl + l * 32768, 128,
                              nullptr, p_t16, 256, N,
                              mlp_b1 + l * 256, bn1_g + l * 256, bn1_b + l * 256,
                              bn1_rm + l * 256, bn1_rv + l * 256,
                              nullptr, 0, nullptr, nullptr);
        dim3 g2(1, gridM);
        k_mma<3, false><<<g2, 256, SMEM_MMA>>>(p_t16, 256, p_wh + 98304 + l * 32768, p_wl + 98304 + l * 32768, 256,
                              p_hcat + (l + 1) * 128, p_hh + (l + 1) * 128, 512, N,
                              mlp_b2 + l * 128, bn2_g + l * 128, bn2_b + l * 128,
                              bn2_rm + l * 128, bn2_rv + l * 128,
                              p_hcat + l * 128, 512, ln_g + l * 128, ln_b + l * 128);
    }

    dim3 go(1, gridM);
    k_mma<1, true><<<go, 256, SMEM_MMA>>>(p_hh, 512, p_wh + 196608, p_wl + 196608, 512,
                          nullptr, p_o16, 128, N,
                          out_b1, nullptr, nullptr, nullptr, nullptr,
                          nullptr, 0, nullptr, nullptr);
    k_mma<0, false><<<go, 256, SMEM_MMA>>>(p_o16, 128, p_wh + 262144, p_wl + 262144, 128,
                          node_emb, nullptr, 128, N,
                          out_b2, nullptr, nullptr, nullptr, nullptr,
                          nullptr, 0, nullptr, nullptr);

    k_pool_acc<<<(N + 127) / 128, 128>>>(node_emb, batch, N);
    k_pool_fin<<<(B * 128 + 255) / 256, 256>>>(graph_emb, B);
}

// round 16
// speedup vs baseline: 1.0145x; 1.0145x over previous
#include <cuda_runtime.h>
#include <cuda_fp16.h>
#include <cstdint>
#include <math.h>

#define MAXN 100000
#define MAXE 600000

// ---------------- scratch (no allocations allowed) ----------------
__device__ __align__(16) float  g_hcat[(size_t)MAXN * 512];   // fp32 h0|h1|h2|h3 per node
__device__ __align__(16) __half g_hh  [(size_t)MAXN * 512];   // fp16 mirror (GEMM A operand)
__device__ __align__(16) __half g_z16 [(size_t)MAXN * 128];
__device__ __align__(16) __half g_t16 [(size_t)MAXN * 256];
__device__ __align__(16) __half g_o16 [(size_t)MAXN * 128];
__device__ int    g_deg   [MAXN];
__device__ int    g_rowptr[MAXN + 1];
__device__ int    g_cursor[MAXN];
__device__ int    g_bsum  [256];
__device__ int    g_boff  [256];
__device__ int    g_srcs  [MAXE];
__device__ __align__(16) float g_sattr[MAXN * 4];
__device__ float  g_gsum  [64 * 128];
__device__ float  g_cnt   [64];
__device__ __align__(16) __half g_wth[278528];
__device__ __align__(16) __half g_wtl[278528];

// ---------------- fused init: weight prep + zeroing + input projection ----------------
__global__ void k_init(const float* __restrict__ x, const float* __restrict__ W,
                       const float* __restrict__ b,
                       const float* __restrict__ W1, const float* __restrict__ W2,
                       const float* __restrict__ O1, const float* __restrict__ O2,
                       int n, int nb) {
    int tid = threadIdx.x;
    int idx = blockIdx.x * 256 + tid;
    // zero
    if (idx < n) g_deg[idx] = 0;
    if (idx < n * 4) g_sattr[idx] = 0.f;
    if (idx < nb * 128) g_gsum[idx] = 0.f;
    if (idx < nb) g_cnt[idx] = 0.f;
    // weight prep (transpose + fp16 hi/lo split)
    if (idx < 278528) {
        const float* src; int K, N, base, rel;
        if (idx < 98304)       { int l = idx / 32768; rel = idx % 32768; src = W1 + (size_t)l * 32768; K = 128; N = 256; base = l * 32768; }
        else if (idx < 196608) { int j = idx - 98304; int l = j / 32768; rel = j % 32768; src = W2 + (size_t)l * 32768; K = 256; N = 128; base = 98304 + l * 32768; }
        else if (idx < 262144) { rel = idx - 196608; src = O1; K = 512; N = 128; base = 196608; }
        else                   { rel = idx - 262144; src = O2; K = 128; N = 128; base = 262144; }
        int k = rel / N, nn = rel % N;
        float v = src[rel];
        __half h = __float2half_rn(v);
        __half l2 = __float2half_rn(v - __half2float(h));
        g_wth[base + nn * K + k] = h;
        g_wtl[base + nn * K + k] = l2;
    }
    // input projection: 2 nodes per block
    int node = blockIdx.x * 2 + (tid >> 7);
    int c = tid & 127;
    __shared__ float xs[2][12];
    if (c < 12 && node < n) xs[tid >> 7][c] = x[node * 12 + c];
    __syncthreads();
    if (node < n) {
        float a = b[c];
#pragma unroll
        for (int k = 0; k < 12; k++) a += xs[tid >> 7][k] * W[k * 128 + c];
        g_hcat[(size_t)node * 512 + c] = a;
        g_hh[(size_t)node * 512 + c] = __float2half_rn(a);
    }
}

// ---------------- CSR build ----------------
__global__ void k_count(const int* __restrict__ dst, const float* __restrict__ ea, int e) {
    int i = blockIdx.x * blockDim.x + threadIdx.x;
    if (i >= e) return;
    int d = dst[i];
    atomicAdd(&g_deg[d], 1);
    atomicAdd(&g_sattr[d * 4 + 0], ea[3 * i]);
    atomicAdd(&g_sattr[d * 4 + 1], ea[3 * i + 1]);
    atomicAdd(&g_sattr[d * 4 + 2], ea[3 * i + 2]);
}
__global__ void k_scan1(int n) {
    int t = threadIdx.x, b = blockIdx.x;
    int i = b * 512 + t;
    int v = (i < n) ? g_deg[i] : 0;
    int lane = t & 31, w = t >> 5;
    int x = v;
#pragma unroll
    for (int o = 1; o < 32; o <<= 1) {
        int y = __shfl_up_sync(0xFFFFFFFFu, x, o);
        if (lane >= o) x += y;
    }
    __shared__ int ws[16];
    if (lane == 31) ws[w] = x;
    __syncthreads();
    if (w == 0) {
        int y = (lane < 16) ? ws[lane] : 0;
#pragma unroll
        for (int o = 1; o < 16; o <<= 1) {
            int z = __shfl_up_sync(0xFFFFFFFFu, y, o);
            if (lane >= o) y += z;
        }
        if (lane < 16) ws[lane] = y;
    }
    __syncthreads();
    int incl = x + (w > 0 ? ws[w - 1] : 0);
    if (i < n) g_rowptr[i] = incl - v;
    if (t == 511) g_bsum[b] = incl;
}
__global__ void k_scan2(int nb) {
    __shared__ int s[256];
    int t = threadIdx.x;
    s[t] = (t < nb) ? g_bsum[t] : 0;
    __syncthreads();
    for (int o = 1; o < 256; o <<= 1) {
        int v = (t >= o) ? s[t - o] : 0;
        __syncthreads();
        s[t] += v;
        __syncthreads();
    }
    g_boff[t] = (t == 0) ? 0 : s[t - 1];
}
__global__ void k_scan3(int n, int e) {
    int i = blockIdx.x * blockDim.x + threadIdx.x;
    if (i < n) {
        int r = g_rowptr[i] + g_boff[i >> 9];
        g_rowptr[i] = r;
        g_cursor[i] = r;
    }
    if (i == 0) g_rowptr[n] = e;
}
__global__ void k_scatter(const int* __restrict__ src, const int* __restrict__ dst, int e) {
    int i = blockIdx.x * blockDim.x + threadIdx.x;
    if (i >= e) return;
    int p = atomicAdd(&g_cursor[dst[i]], 1);
    g_srcs[p] = src[i];
}

// ---------------- aggregation ----------------
__global__ void k_aggregate(const float* __restrict__ edgeW, const float* __restrict__ edgeb,
                            const float* __restrict__ eps, int l, int n) {
    int gid = blockIdx.x * blockDim.x + threadIdx.x;
    int node = gid >> 5, lane = gid & 31;
    if (node >= n) return;
    int c = lane * 4;
    float4 w0 = *(const float4*)(edgeW + c);
    float4 w1 = *(const float4*)(edgeW + 128 + c);
    float4 w2 = *(const float4*)(edgeW + 256 + c);
    float4 eb = *(const float4*)(edgeb + c);
    float ep = 1.f + eps[l];
    const float* hb = g_hcat + (size_t)l * 128;
    float4 hh = *(const float4*)(hb + (size_t)node * 512 + c);
    float4 sa = *(const float4*)(g_sattr + node * 4);
    int j0 = g_rowptr[node], j1 = g_rowptr[node + 1];
    float dg = (float)(j1 - j0);
    float4 acc;
    acc.x = ep * hh.x + sa.x * w0.x + sa.y * w1.x + sa.z * w2.x + dg * eb.x;
    acc.y = ep * hh.y + sa.x * w0.y + sa.y * w1.y + sa.z * w2.y + dg * eb.y;
    acc.z = ep * hh.z + sa.x * w0.z + sa.y * w1.z + sa.z * w2.z + dg * eb.z;
    acc.w = ep * hh.w + sa.x * w0.w + sa.y * w1.w + sa.z * w2.w + dg * eb.w;
    for (int j = j0; j < j1; j++) {
        int s = g_srcs[j];
        float4 hs = *(const float4*)(hb + (size_t)s * 512 + c);
        acc.x += hs.x; acc.y += hs.y; acc.z += hs.z; acc.w += hs.w;
    }
    __half2 h0 = __floats2half2_rn(acc.x, acc.y);
    __half2 h1 = __floats2half2_rn(acc.z, acc.w);
    uint2 o; o.x = *(uint32_t*)&h0; o.y = *(uint32_t*)&h1;
    *(uint2*)(g_z16 + (size_t)node * 128 + c) = o;
}

// ---------------- tensor-core GEMM (fp16 A + split-B, 2-stage cp.async) ----------------
__device__ __forceinline__ void mma16816(float* c, const unsigned* a, const unsigned* b) {
    asm volatile(
        "mma.sync.aligned.m16n8k16.row.col.f32.f16.f16.f32 "
        "{%0,%1,%2,%3}, {%4,%5,%6,%7}, {%8,%9}, {%0,%1,%2,%3};\n"
        : "+f"(c[0]), "+f"(c[1]), "+f"(c[2]), "+f"(c[3])
        : "r"(a[0]), "r"(a[1]), "r"(a[2]), "r"(a[3]), "r"(b[0]), "r"(b[1]));
}
__device__ __forceinline__ void ldm_x4(unsigned* r, uint32_t a) {
    asm volatile("ldmatrix.sync.aligned.m8n8.x4.shared.b16 {%0,%1,%2,%3}, [%4];"
        : "=r"(r[0]), "=r"(r[1]), "=r"(r[2]), "=r"(r[3]) : "r"(a));
}
__device__ __forceinline__ uint32_t smem_u32(const void* p) {
    uint32_t a;
    asm("{ .reg .u64 t; cvta.to.shared.u64 t, %1; cvt.u32.u64 %0, t; }" : "=r"(a) : "l"(p));
    return a;
}
__device__ __forceinline__ void cpa16(uint32_t s, const void* g) {
    asm volatile("cp.async.cg.shared.global [%0], [%1], 16;" :: "r"(s), "l"(g));
}
#define CPA_COMMIT() asm volatile("cp.async.commit_group;" ::: "memory")
#define CPA_WAIT0()  asm volatile("cp.async.wait_group 0;" ::: "memory")

#define SMS 40
#define BUFB 10240u
#define OF_A(s)  ((s) * BUFB)
#define OF_BH(s) (2u * BUFB + (s) * BUFB)
#define OF_BL(s) (4u * BUFB + (s) * BUFB)
#define OF_RED   (6u * BUFB)
#define SMEM_MMA (6 * 10240 + 2048)   // 63488

// EPI: 0=+bias, 1=relu(+bias), 2=relu(BN(+bias)), 3=relu(BN(+bias))+Res+LN (grid.x==1)
template<int EPI, bool O16>
__global__ __launch_bounds__(256, 2) void k_mma(
    const __half* __restrict__ A, int lda,
    const __half* __restrict__ Wh, const __half* __restrict__ Wl, int K,
    float* __restrict__ C, __half* __restrict__ C16, int ldc, int M,
    const float* __restrict__ bias,
    const float* __restrict__ bng, const float* __restrict__ bnb,
    const float* __restrict__ bnrm, const float* __restrict__ bnrv,
    const float* __restrict__ Res, int ldr,
    const float* __restrict__ lng, const float* __restrict__ lnb) {
    extern __shared__ __align__(16) char smx[];
    uint32_t smb = smem_u32(smx);
    float* sRedP = (float*)(smx + OF_RED);

    int tid = threadIdx.x, lane = tid & 31, wid = tid >> 5;
    int wy = wid & 3, wx = wid >> 2;
    int mW = wy * 32, nW = wx * 64;
    int g = lane >> 2, qt = lane & 3;
    int rowBase = blockIdx.y * 128, colBase = blockIdx.x * 128;

    float c[2][8][4];
#pragma unroll
    for (int i = 0; i < 2; i++)
#pragma unroll
        for (int j = 0; j < 8; j++)
#pragma unroll
            for (int m = 0; m < 4; m++) c[i][j][m] = 0.f;

    uint32_t aOff = (uint32_t)((mW + (lane & 15)) * SMS + ((lane >> 4) << 3)) * 2;
    uint32_t bOff = (uint32_t)((nW + ((lane >> 4) << 3) + (lane & 7)) * SMS + (((lane >> 3) & 1) << 3)) * 2;

    uint32_t tSm[2];
    size_t aGm[2], bGm[2];
#pragma unroll
    for (int i = 0; i < 2; i++) {
        int v = tid + i * 256;
        int r = v >> 2, kc8 = (v & 3) * 8;
        tSm[i] = (uint32_t)(r * SMS + kc8) * 2;
        int ar = rowBase + r; if (ar >= M) ar = M - 1;
        aGm[i] = (size_t)ar * lda + kc8;
        bGm[i] = (size_t)(colBase + r) * K + kc8;
    }

    // prologue: tile 0
#pragma unroll
    for (int i = 0; i < 2; i++) {
        cpa16(smb + OF_A(0)  + tSm[i], A  + aGm[i]);
        cpa16(smb + OF_BH(0) + tSm[i], Wh + bGm[i]);
        cpa16(smb + OF_BL(0) + tSm[i], Wl + bGm[i]);
    }
    CPA_COMMIT();

    int nk = K >> 5;
    for (int t = 0; t < nk; t++) {
        int cur = t & 1, nxt = cur ^ 1;
        CPA_WAIT0();
        __syncthreads();
        if (t + 1 < nk) {
            int k0 = (t + 1) << 5;
#pragma unroll
            for (int i = 0; i < 2; i++) {
                cpa16(smb + OF_A(nxt)  + tSm[i], A  + aGm[i] + k0);
                cpa16(smb + OF_BH(nxt) + tSm[i], Wh + bGm[i] + k0);
                cpa16(smb + OF_BL(nxt) + tSm[i], Wl + bGm[i] + k0);
            }
            CPA_COMMIT();
        }
        uint32_t aB  = smb + OF_A(cur)  + aOff;
        uint32_t bhB = smb + OF_BH(cur) + bOff;
        uint32_t blB = smb + OF_BL(cur) + bOff;
#pragma unroll
        for (int kc = 0; kc < 2; kc++) {
            uint32_t kByte = (uint32_t)(kc * 16) * 2;
            unsigned ah[2][4], bh[8][2], bl[8][2];
#pragma unroll
            for (int i = 0; i < 2; i++)
                ldm_x4(ah[i], aB + (uint32_t)(i * 16 * SMS) * 2 + kByte);
#pragma unroll
            for (int j2 = 0; j2 < 4; j2++) {
                uint32_t rb = (uint32_t)(j2 * 16 * SMS) * 2 + kByte;
                ldm_x4(&bh[j2 * 2][0], bhB + rb);
                ldm_x4(&bl[j2 * 2][0], blB + rb);
            }
#pragma unroll
            for (int i = 0; i < 2; i++)
#pragma unroll
                for (int j = 0; j < 8; j++) {
                    mma16816(c[i][j], ah[i], bh[j]);
                    mma16816(c[i][j], ah[i], bl[j]);
                }
        }
    }
    __syncthreads();

    float cs[8][2], ct[8][2];
#pragma unroll
    for (int j = 0; j < 8; j++) {
#pragma unroll
        for (int h = 0; h < 2; h++) {
            int col = colBase + nW + j * 8 + qt * 2 + h;
            if (EPI >= 2) {
                float s = bng[col] * rsqrtf(bnrv[col] + 1e-5f);
                cs[j][h] = s; ct[j][h] = bnb[col] + (bias[col] - bnrm[col]) * s;
            } else { cs[j][h] = 1.f; ct[j][h] = bias[col]; }
        }
    }

    if (EPI == 3) {
        float s[2][2], q[2][2];
#pragma unroll
        for (int i = 0; i < 2; i++) { s[i][0] = s[i][1] = 0.f; q[i][0] = q[i][1] = 0.f; }
#pragma unroll
        for (int i = 0; i < 2; i++) {
            int r1 = rowBase + mW + i * 16 + g, r2 = r1 + 8;
#pragma unroll
            for (int j = 0; j < 8; j++) {
                int colL = nW + j * 8 + qt * 2;
                float2 res1 = make_float2(0.f, 0.f), res2 = make_float2(0.f, 0.f);
                if (r1 < M) res1 = *(const float2*)(Res + (size_t)r1 * ldr + colL);
                if (r2 < M) res2 = *(const float2*)(Res + (size_t)r2 * ldr + colL);
                float v0 = fmaxf(c[i][j][0] * cs[j][0] + ct[j][0], 0.f) + res1.x;
                float v1 = fmaxf(c[i][j][1] * cs[j][1] + ct[j][1], 0.f) + res1.y;
                float v2 = fmaxf(c[i][j][2] * cs[j][0] + ct[j][0], 0.f) + res2.x;
                float v3 = fmaxf(c[i][j][3] * cs[j][1] + ct[j][1], 0.f) + res2.y;
                c[i][j][0] = v0; c[i][j][1] = v1; c[i][j][2] = v2; c[i][j][3] = v3;
                s[i][0] += v0 + v1; q[i][0] += v0 * v0 + v1 * v1;
                s[i][1] += v2 + v3; q[i][1] += v2 * v2 + v3 * v3;
            }
        }
#pragma unroll
        for (int i = 0; i < 2; i++)
#pragma unroll
            for (int h = 0; h < 2; h++) {
                s[i][h] += __shfl_xor_sync(0xFFFFFFFFu, s[i][h], 1);
                s[i][h] += __shfl_xor_sync(0xFFFFFFFFu, s[i][h], 2);
                q[i][h] += __shfl_xor_sync(0xFFFFFFFFu, q[i][h], 1);
                q[i][h] += __shfl_xor_sync(0xFFFFFFFFu, q[i][h], 2);
            }
        if (qt == 0) {
#pragma unroll
            for (int i = 0; i < 2; i++)
#pragma unroll
                for (int h = 0; h < 2; h++) {
                    int lr = mW + i * 16 + g + h * 8;
                    sRedP[lr * 2 + wx]       = s[i][h];
                    sRedP[256 + lr * 2 + wx] = q[i][h];
                }
        }
        __syncthreads();
#pragma unroll
        for (int i = 0; i < 2; i++)
#pragma unroll
            for (int h = 0; h < 2; h++) {
                int lr = mW + i * 16 + g + h * 8;
                int gr = rowBase + lr;
                float ts = sRedP[lr * 2] + sRedP[lr * 2 + 1];
                float tq = sRedP[256 + lr * 2] + sRedP[256 + lr * 2 + 1];
                float mu = ts * (1.f / 128.f);
                float var = tq * (1.f / 128.f) - mu * mu;
                float rr = rsqrtf(var + 1e-5f);
                if (gr < M) {
#pragma unroll
                    for (int j = 0; j < 8; j++) {
                        int colL = nW + j * 8 + qt * 2;
                        float2 o;
                        o.x = (c[i][j][h * 2]     - mu) * rr * lng[colL]     + lnb[colL];
                        o.y = (c[i][j][h * 2 + 1] - mu) * rr * lng[colL + 1] + lnb[colL + 1];
                        *(float2*)(C + (size_t)gr * ldc + colL) = o;
                        __half2 oh = __floats2half2_rn(o.x, o.y);
                        *(uint32_t*)(C16 + (size_t)gr * ldc + colL) = *(uint32_t*)&oh;
                    }
                }
            }
    } else {
#pragma unroll
        for (int i = 0; i < 2; i++) {
            int r1 = rowBase + mW + i * 16 + g, r2 = r1 + 8;
#pragma unroll
            for (int j = 0; j < 8; j++) {
                int col = colBase + nW + j * 8 + qt * 2;
                float o0 = c[i][j][0] * cs[j][0] + ct[j][0];
                float o1 = c[i][j][1] * cs[j][1] + ct[j][1];
                float o2 = c[i][j][2] * cs[j][0] + ct[j][0];
                float o3 = c[i][j][3] * cs[j][1] + ct[j][1];
                if (EPI >= 1) {
                    o0 = fmaxf(o0, 0.f); o1 = fmaxf(o1, 0.f);
                    o2 = fmaxf(o2, 0.f); o3 = fmaxf(o3, 0.f);
                }
                if (O16) {
                    if (r1 < M) { __half2 oh = __floats2half2_rn(o0, o1);
                        *(uint32_t*)(C16 + (size_t)r1 * ldc + col) = *(uint32_t*)&oh; }
                    if (r2 < M) { __half2 oh = __floats2half2_rn(o2, o3);
                        *(uint32_t*)(C16 + (size_t)r2 * ldc + col) = *(uint32_t*)&oh; }
                } else {
                    if (r1 < M) { float2 o; o.x = o0; o.y = o1; *(float2*)(C + (size_t)r1 * ldc + col) = o; }
                    if (r2 < M) { float2 o; o.x = o2; o.y = o3; *(float2*)(C + (size_t)r2 * ldc + col) = o; }
                }
            }
        }
    }
}

// ---------------- global mean pool ----------------
__global__ void k_pool_acc(const float* __restrict__ emb, const int* __restrict__ batch, int n) {
    int c = threadIdx.x;
    int base = blockIdx.x * 64;
    float acc = 0.f, cnt = 0.f;
    int cur = -1;
    for (int i = 0; i < 64; i++) {
        int nd = base + i;
        if (nd >= n) break;
        int g = batch[nd];
        if (g != cur) {
            if (cur >= 0) {
                atomicAdd(&g_gsum[cur * 128 + c], acc);
                if (c == 0) atomicAdd(&g_cnt[cur], cnt);
            }
            cur = g; acc = 0.f; cnt = 0.f;
        }
        acc += emb[(size_t)nd * 128 + c];
        cnt += 1.f;
    }
    if (cur >= 0) {
        atomicAdd(&g_gsum[cur * 128 + c], acc);
        if (c == 0) atomicAdd(&g_cnt[cur], cnt);
    }
}
__global__ void k_pool_fin(float* __restrict__ out, int b) {
    int i = blockIdx.x * blockDim.x + threadIdx.x;
    if (i >= b * 128) return;
    out[i] = g_gsum[i] / fmaxf(g_cnt[i >> 7], 1.f);
}

// ---------------- launch ----------------
extern "C" void kernel_launch(void* const* d_in, const int* in_sizes, int n_in,
                              void* d_out, int out_size) {
    const float* x      = (const float*)d_in[0];
    const int*   ei     = (const int*)d_in[1];
    const float* ea     = (const float*)d_in[2];
    const int*   batch  = (const int*)d_in[3];
    const float* in_W   = (const float*)d_in[4];
    const float* in_b   = (const float*)d_in[5];
    const float* edge_W = (const float*)d_in[6];
    const float* edge_b = (const float*)d_in[7];
    const float* mlp_W1 = (const float*)d_in[8];
    const float* mlp_b1 = (const float*)d_in[9];
    const float* bn1_g  = (const float*)d_in[10];
    const float* bn1_b  = (const float*)d_in[11];
    const float* bn1_rm = (const float*)d_in[12];
    const float* bn1_rv = (const float*)d_in[13];
    const float* mlp_W2 = (const float*)d_in[14];
    const float* mlp_b2 = (const float*)d_in[15];
    const float* bn2_g  = (const float*)d_in[16];
    const float* bn2_b  = (const float*)d_in[17];
    const float* bn2_rm = (const float*)d_in[18];
    const float* bn2_rv = (const float*)d_in[19];
    const float* eps    = (const float*)d_in[20];
    const float* ln_g   = (const float*)d_in[21];
    const float* ln_b   = (const float*)d_in[22];
    const float* out_W1 = (const float*)d_in[23];
    const float* out_b1 = (const float*)d_in[24];
    const float* out_W2 = (const float*)d_in[25];
    const float* out_b2 = (const float*)d_in[26];

    int N = in_sizes[0] / 12;
    int E = in_sizes[2] / 3;
    int B = out_size / 128 - N;
    const int* src = ei;
    const int* dst = ei + E;
    float* node_emb  = (float*)d_out;
    float* graph_emb = node_emb + (size_t)N * 128;

    float *p_hcat;
    __half *p_wh, *p_wl, *p_hh, *p_z16, *p_t16, *p_o16;
    cudaGetSymbolAddress((void**)&p_hcat, g_hcat);
    cudaGetSymbolAddress((void**)&p_hh,   g_hh);
    cudaGetSymbolAddress((void**)&p_z16,  g_z16);
    cudaGetSymbolAddress((void**)&p_t16,  g_t16);
    cudaGetSymbolAddress((void**)&p_o16,  g_o16);
    cudaGetSymbolAddress((void**)&p_wh,   g_wth);
    cudaGetSymbolAddress((void**)&p_wl,   g_wtl);

    cudaFuncSetAttribute(k_mma<0, false>, cudaFuncAttributeMaxDynamicSharedMemorySize, SMEM_MMA);
    cudaFuncSetAttribute(k_mma<1, true>,  cudaFuncAttributeMaxDynamicSharedMemorySize, SMEM_MMA);
    cudaFuncSetAttribute(k_mma<2, true>,  cudaFuncAttributeMaxDynamicSharedMemorySize, SMEM_MMA);
    cudaFuncSetAttribute(k_mma<3, false>, cudaFuncAttributeMaxDynamicSharedMemorySize, SMEM_MMA);

    // fused init: prep + zero + in_proj (one launch)
    int gInit = (N + 1) / 2;
    if (gInit < 1089) gInit = 1089;
    k_init<<<gInit, 256>>>(x, in_W, in_b, mlp_W1, mlp_W2, out_W1, out_W2, N, B);

    k_count<<<(E + 255) / 256, 256>>>(dst, ea, E);
    int nb = (N + 511) / 512;
    k_scan1<<<nb, 512>>>(N);
    k_scan2<<<1, 256>>>(nb);
    k_scan3<<<(N + 255) / 256, 256>>>(N, E);
    k_scatter<<<(E + 255) / 256, 256>>>(src, dst, E);

    int gridM = (N + 127) / 128;
    for (int l = 0; l < 3; l++) {
        k_aggregate<<<(N * 32 + 255) / 256, 256>>>(edge_W + l * 384, edge_b + l * 128, eps, l, N);
        dim3 g1(2, gridM);
        k_mma<2, true><<<g1, 256, SMEM_MMA>>>(p_z16, 128, p_wh + l * 32768, p_wl + l * 32768, 128,
                              nullptr, p_t16, 256, N,
                              mlp_b1 + l * 256, bn1_g + l * 256, bn1_b + l * 256,
                              bn1_rm + l * 256, bn1_rv + l * 256,
                              nullptr, 0, nullptr, nullptr);
        dim3 g2(1, gridM);
        k_mma<3, false><<<g2, 256, SMEM_MMA>>>(p_t16, 256, p_wh + 98304 + l * 32768, p_wl + 98304 + l * 32768, 256,
                              p_hcat + (l + 1) * 128, p_hh + (l + 1) * 128, 512, N,
                              mlp_b2 + l * 128, bn2_g + l * 128, bn2_b + l * 128,
                              bn2_rm + l * 128, bn2_rv + l * 128,
                              p_hcat + l * 128, 512, ln_g + l * 128, ln_b + l * 128);
    }

    dim3 go(1, gridM);
    k_mma<1, true><<<go, 256, SMEM_MMA>>>(p_hh, 512, p_wh + 196608, p_wl + 196608, 512,
                          nullptr, p_o16, 128, N,
                          out_b1, nullptr, nullptr, nullptr, nullptr,
                          nullptr, 0, nullptr, nullptr);
    k_mma<0, false><<<go, 256, SMEM_MMA>>>(p_o16, 128, p_wh + 262144, p_wl + 262144, 128,
                          node_emb, nullptr, 128, N,
                          out_b2, nullptr, nullptr, nullptr, nullptr,
                          nullptr, 0, nullptr, nullptr);

    k_pool_acc<<<(N + 63) / 64, 128>>>(node_emb, batch, N);
    k_pool_fin<<<(B * 128 + 255) / 256, 256>>>(graph_emb, B);
}

// round 17
// speedup vs baseline: 1.0235x; 1.0089x over previous
#include <cuda_runtime.h>
#include <cuda_fp16.h>
#include <cstdint>
#include <math.h>

#define MAXN 100000
#define MAXE 600000

// ---------------- scratch (no allocations allowed) ----------------
__device__ __align__(16) float  g_hcat[(size_t)MAXN * 512];   // fp32 h0|h1|h2|h3 per node
__device__ __align__(16) __half g_hh  [(size_t)MAXN * 512];   // fp16 mirror (GEMM A operand)
__device__ __align__(16) __half g_z16 [(size_t)MAXN * 128];
__device__ __align__(16) __half g_t16 [(size_t)MAXN * 256];
__device__ __align__(16) __half g_o16 [(size_t)MAXN * 128];
__device__ int    g_deg   [MAXN];
__device__ int    g_rowptr[MAXN + 1];
__device__ int    g_cursor[MAXN];
__device__ int    g_bsum  [256];
__device__ int    g_boff  [256];
__device__ int    g_srcs  [MAXE];
__device__ __align__(16) float g_sattr[MAXN * 4];
__device__ float  g_gsum  [64 * 128];
__device__ float  g_cnt   [64];
__device__ __align__(16) __half g_wth[278528];
__device__ __align__(16) __half g_wtl[278528];

// ---------------- fused init: weight prep + zeroing + input projection ----------------
__global__ void k_init(const float* __restrict__ x, const float* __restrict__ W,
                       const float* __restrict__ b,
                       const float* __restrict__ W1, const float* __restrict__ W2,
                       const float* __restrict__ O1, const float* __restrict__ O2,
                       int n, int nb) {
    int tid = threadIdx.x;
    int idx = blockIdx.x * 256 + tid;
    // zero
    if (idx < n) g_deg[idx] = 0;
    if (idx < n * 4) g_sattr[idx] = 0.f;
    if (idx < nb * 128) g_gsum[idx] = 0.f;
    if (idx < nb) g_cnt[idx] = 0.f;
    // weight prep (transpose + fp16 hi/lo split)
    if (idx < 278528) {
        const float* src; int K, N, base, rel;
        if (idx < 98304)       { int l = idx / 32768; rel = idx % 32768; src = W1 + (size_t)l * 32768; K = 128; N = 256; base = l * 32768; }
        else if (idx < 196608) { int j = idx - 98304; int l = j / 32768; rel = j % 32768; src = W2 + (size_t)l * 32768; K = 256; N = 128; base = 98304 + l * 32768; }
        else if (idx < 262144) { rel = idx - 196608; src = O1; K = 512; N = 128; base = 196608; }
        else                   { rel = idx - 262144; src = O2; K = 128; N = 128; base = 262144; }
        int k = rel / N, nn = rel % N;
        float v = src[rel];
        __half h = __float2half_rn(v);
        __half l2 = __float2half_rn(v - __half2float(h));
        g_wth[base + nn * K + k] = h;
        g_wtl[base + nn * K + k] = l2;
    }
    // input projection: 2 nodes per block
    int node = blockIdx.x * 2 + (tid >> 7);
    int c = tid & 127;
    __shared__ float xs[2][12];
    if (c < 12 && node < n) xs[tid >> 7][c] = x[node * 12 + c];
    __syncthreads();
    if (node < n) {
        float a = b[c];
#pragma unroll
        for (int k = 0; k < 12; k++) a += xs[tid >> 7][k] * W[k * 128 + c];
        g_hcat[(size_t)node * 512 + c] = a;
        g_hh[(size_t)node * 512 + c] = __float2half_rn(a);
    }
}

// ---------------- CSR build ----------------
__global__ void k_count(const int* __restrict__ dst, const float* __restrict__ ea, int e) {
    int i = blockIdx.x * blockDim.x + threadIdx.x;
    if (i >= e) return;
    int d = dst[i];
    atomicAdd(&g_deg[d], 1);
    atomicAdd(&g_sattr[d * 4 + 0], ea[3 * i]);
    atomicAdd(&g_sattr[d * 4 + 1], ea[3 * i + 1]);
    atomicAdd(&g_sattr[d * 4 + 2], ea[3 * i + 2]);
}
__global__ void k_scan1(int n) {
    int t = threadIdx.x, b = blockIdx.x;
    int i = b * 512 + t;
    int v = (i < n) ? g_deg[i] : 0;
    int lane = t & 31, w = t >> 5;
    int x = v;
#pragma unroll
    for (int o = 1; o < 32; o <<= 1) {
        int y = __shfl_up_sync(0xFFFFFFFFu, x, o);
        if (lane >= o) x += y;
    }
    __shared__ int ws[16];
    if (lane == 31) ws[w] = x;
    __syncthreads();
    if (w == 0) {
        int y = (lane < 16) ? ws[lane] : 0;
#pragma unroll
        for (int o = 1; o < 16; o <<= 1) {
            int z = __shfl_up_sync(0xFFFFFFFFu, y, o);
            if (lane >= o) y += z;
        }
        if (lane < 16) ws[lane] = y;
    }
    __syncthreads();
    int incl = x + (w > 0 ? ws[w - 1] : 0);
    if (i < n) g_rowptr[i] = incl - v;
    if (t == 511) g_bsum[b] = incl;
}
__global__ void k_scan2(int nb) {
    __shared__ int s[256];
    int t = threadIdx.x;
    s[t] = (t < nb) ? g_bsum[t] : 0;
    __syncthreads();
    for (int o = 1; o < 256; o <<= 1) {
        int v = (t >= o) ? s[t - o] : 0;
        __syncthreads();
        s[t] += v;
        __syncthreads();
    }
    g_boff[t] = (t == 0) ? 0 : s[t - 1];
}
__global__ void k_scan3(int n, int e) {
    int i = blockIdx.x * blockDim.x + threadIdx.x;
    if (i < n) {
        int r = g_rowptr[i] + g_boff[i >> 9];
        g_rowptr[i] = r;
        g_cursor[i] = r;
    }
    if (i == 0) g_rowptr[n] = e;
}
__global__ void k_scatter(const int* __restrict__ src, const int* __restrict__ dst, int e) {
    int i = blockIdx.x * blockDim.x + threadIdx.x;
    if (i >= e) return;
    int p = atomicAdd(&g_cursor[dst[i]], 1);
    g_srcs[p] = src[i];
}

// ---------------- aggregation ----------------
__global__ void k_aggregate(const float* __restrict__ edgeW, const float* __restrict__ edgeb,
                            const float* __restrict__ eps, int l, int n) {
    int gid = blockIdx.x * blockDim.x + threadIdx.x;
    int node = gid >> 5, lane = gid & 31;
    if (node >= n) return;
    int c = lane * 4;
    float4 w0 = *(const float4*)(edgeW + c);
    float4 w1 = *(const float4*)(edgeW + 128 + c);
    float4 w2 = *(const float4*)(edgeW + 256 + c);
    float4 eb = *(const float4*)(edgeb + c);
    float ep = 1.f + eps[l];
    const float* hb = g_hcat + (size_t)l * 128;
    float4 hh = *(const float4*)(hb + (size_t)node * 512 + c);
    float4 sa = *(const float4*)(g_sattr + node * 4);
    int j0 = g_rowptr[node], j1 = g_rowptr[node + 1];
    float dg = (float)(j1 - j0);
    float4 acc;
    acc.x = ep * hh.x + sa.x * w0.x + sa.y * w1.x + sa.z * w2.x + dg * eb.x;
    acc.y = ep * hh.y + sa.x * w0.y + sa.y * w1.y + sa.z * w2.y + dg * eb.y;
    acc.z = ep * hh.z + sa.x * w0.z + sa.y * w1.z + sa.z * w2.z + dg * eb.z;
    acc.w = ep * hh.w + sa.x * w0.w + sa.y * w1.w + sa.z * w2.w + dg * eb.w;
    for (int j = j0; j < j1; j++) {
        int s = g_srcs[j];
        float4 hs = *(const float4*)(hb + (size_t)s * 512 + c);
        acc.x += hs.x; acc.y += hs.y; acc.z += hs.z; acc.w += hs.w;
    }
    __half2 h0 = __floats2half2_rn(acc.x, acc.y);
    __half2 h1 = __floats2half2_rn(acc.z, acc.w);
    uint2 o; o.x = *(uint32_t*)&h0; o.y = *(uint32_t*)&h1;
    *(uint2*)(g_z16 + (size_t)node * 128 + c) = o;
}

// ---------------- tensor-core GEMM (fp16 A + split-B, 2-stage cp.async) ----------------
__device__ __forceinline__ void mma16816(float* c, const unsigned* a, const unsigned* b) {
    asm volatile(
        "mma.sync.aligned.m16n8k16.row.col.f32.f16.f16.f32 "
        "{%0,%1,%2,%3}, {%4,%5,%6,%7}, {%8,%9}, {%0,%1,%2,%3};\n"
        : "+f"(c[0]), "+f"(c[1]), "+f"(c[2]), "+f"(c[3])
        : "r"(a[0]), "r"(a[1]), "r"(a[2]), "r"(a[3]), "r"(b[0]), "r"(b[1]));
}
__device__ __forceinline__ void ldm_x4(unsigned* r, uint32_t a) {
    asm volatile("ldmatrix.sync.aligned.m8n8.x4.shared.b16 {%0,%1,%2,%3}, [%4];"
        : "=r"(r[0]), "=r"(r[1]), "=r"(r[2]), "=r"(r[3]) : "r"(a));
}
__device__ __forceinline__ uint32_t smem_u32(const void* p) {
    uint32_t a;
    asm("{ .reg .u64 t; cvta.to.shared.u64 t, %1; cvt.u32.u64 %0, t; }" : "=r"(a) : "l"(p));
    return a;
}
__device__ __forceinline__ void cpa16(uint32_t s, const void* g) {
    asm volatile("cp.async.cg.shared.global [%0], [%1], 16;" :: "r"(s), "l"(g));
}
#define CPA_COMMIT() asm volatile("cp.async.commit_group;" ::: "memory")
#define CPA_WAIT0()  asm volatile("cp.async.wait_group 0;" ::: "memory")

#define SMS 40
#define BUFB 10240u
#define OF_A(s)  ((s) * BUFB)
#define OF_BH(s) (2u * BUFB + (s) * BUFB)
#define OF_BL(s) (4u * BUFB + (s) * BUFB)
#define OF_RED   (6u * BUFB)
#define SMEM_MMA (6 * 10240 + 2048)   // 63488

// EPI: 0=+bias, 1=relu(+bias), 2=relu(BN(+bias)), 3=relu(BN(+bias))+Res+LN (grid.x==1)
template<int EPI, bool O16>
__global__ __launch_bounds__(256, 2) void k_mma(
    const __half* __restrict__ A, int lda,
    const __half* __restrict__ Wh, const __half* __restrict__ Wl, int K,
    float* __restrict__ C, __half* __restrict__ C16, int ldc, int M,
    const float* __restrict__ bias,
    const float* __restrict__ bng, const float* __restrict__ bnb,
    const float* __restrict__ bnrm, const float* __restrict__ bnrv,
    const float* __restrict__ Res, int ldr,
    const float* __restrict__ lng, const float* __restrict__ lnb) {
    extern __shared__ __align__(16) char smx[];
    uint32_t smb = smem_u32(smx);
    float* sRedP = (float*)(smx + OF_RED);

    int tid = threadIdx.x, lane = tid & 31, wid = tid >> 5;
    int wy = wid & 3, wx = wid >> 2;
    int mW = wy * 32, nW = wx * 64;
    int g = lane >> 2, qt = lane & 3;
    int rowBase = blockIdx.y * 128, colBase = blockIdx.x * 128;

    float c[2][8][4];
#pragma unroll
    for (int i = 0; i < 2; i++)
#pragma unroll
        for (int j = 0; j < 8; j++)
#pragma unroll
            for (int m = 0; m < 4; m++) c[i][j][m] = 0.f;

    uint32_t aOff = (uint32_t)((mW + (lane & 15)) * SMS + ((lane >> 4) << 3)) * 2;
    uint32_t bOff = (uint32_t)((nW + ((lane >> 4) << 3) + (lane & 7)) * SMS + (((lane >> 3) & 1) << 3)) * 2;

    uint32_t tSm[2];
    size_t aGm[2], bGm[2];
#pragma unroll
    for (int i = 0; i < 2; i++) {
        int v = tid + i * 256;
        int r = v >> 2, kc8 = (v & 3) * 8;
        tSm[i] = (uint32_t)(r * SMS + kc8) * 2;
        int ar = rowBase + r; if (ar >= M) ar = M - 1;
        aGm[i] = (size_t)ar * lda + kc8;
        bGm[i] = (size_t)(colBase + r) * K + kc8;
    }

    // prologue: tile 0
#pragma unroll
    for (int i = 0; i < 2; i++) {
        cpa16(smb + OF_A(0)  + tSm[i], A  + aGm[i]);
        cpa16(smb + OF_BH(0) + tSm[i], Wh + bGm[i]);
        cpa16(smb + OF_BL(0) + tSm[i], Wl + bGm[i]);
    }
    CPA_COMMIT();

    int nk = K >> 5;
    for (int t = 0; t < nk; t++) {
        int cur = t & 1, nxt = cur ^ 1;
        CPA_WAIT0();
        __syncthreads();
        if (t + 1 < nk) {
            int k0 = (t + 1) << 5;
#pragma unroll
            for (int i = 0; i < 2; i++) {
                cpa16(smb + OF_A(nxt)  + tSm[i], A  + aGm[i] + k0);
                cpa16(smb + OF_BH(nxt) + tSm[i], Wh + bGm[i] + k0);
                cpa16(smb + OF_BL(nxt) + tSm[i], Wl + bGm[i] + k0);
            }
            CPA_COMMIT();
        }
        uint32_t aB  = smb + OF_A(cur)  + aOff;
        uint32_t bhB = smb + OF_BH(cur) + bOff;
        uint32_t blB = smb + OF_BL(cur) + bOff;
#pragma unroll
        for (int kc = 0; kc < 2; kc++) {
            uint32_t kByte = (uint32_t)(kc * 16) * 2;
            unsigned ah[2][4], bh[8][2], bl[8][2];
#pragma unroll
            for (int i = 0; i < 2; i++)
                ldm_x4(ah[i], aB + (uint32_t)(i * 16 * SMS) * 2 + kByte);
#pragma unroll
            for (int j2 = 0; j2 < 4; j2++) {
                uint32_t rb = (uint32_t)(j2 * 16 * SMS) * 2 + kByte;
                ldm_x4(&bh[j2 * 2][0], bhB + rb);
                ldm_x4(&bl[j2 * 2][0], blB + rb);
            }
#pragma unroll
            for (int i = 0; i < 2; i++)
#pragma unroll
                for (int j = 0; j < 8; j++) {
                    mma16816(c[i][j], ah[i], bh[j]);
                    mma16816(c[i][j], ah[i], bl[j]);
                }
        }
    }
    __syncthreads();

    float cs[8][2], ct[8][2];
#pragma unroll
    for (int j = 0; j < 8; j++) {
#pragma unroll
        for (int h = 0; h < 2; h++) {
            int col = colBase + nW + j * 8 + qt * 2 + h;
            if (EPI >= 2) {
                float s = bng[col] * rsqrtf(bnrv[col] + 1e-5f);
                cs[j][h] = s; ct[j][h] = bnb[col] + (bias[col] - bnrm[col]) * s;
            } else { cs[j][h] = 1.f; ct[j][h] = bias[col]; }
        }
    }

    if (EPI == 3) {
        float s[2][2], q[2][2];
#pragma unroll
        for (int i = 0; i < 2; i++) { s[i][0] = s[i][1] = 0.f; q[i][0] = q[i][1] = 0.f; }
#pragma unroll
        for (int i = 0; i < 2; i++) {
            int r1 = rowBase + mW + i * 16 + g, r2 = r1 + 8;
#pragma unroll
            for (int j = 0; j < 8; j++) {
                int colL = nW + j * 8 + qt * 2;
                float2 res1 = make_float2(0.f, 0.f), res2 = make_float2(0.f, 0.f);
                if (r1 < M) res1 = *(const float2*)(Res + (size_t)r1 * ldr + colL);
                if (r2 < M) res2 = *(const float2*)(Res + (size_t)r2 * ldr + colL);
                float v0 = fmaxf(c[i][j][0] * cs[j][0] + ct[j][0], 0.f) + res1.x;
                float v1 = fmaxf(c[i][j][1] * cs[j][1] + ct[j][1], 0.f) + res1.y;
                float v2 = fmaxf(c[i][j][2] * cs[j][0] + ct[j][0], 0.f) + res2.x;
                float v3 = fmaxf(c[i][j][3] * cs[j][1] + ct[j][1], 0.f) + res2.y;
                c[i][j][0] = v0; c[i][j][1] = v1; c[i][j][2] = v2; c[i][j][3] = v3;
                s[i][0] += v0 + v1; q[i][0] += v0 * v0 + v1 * v1;
                s[i][1] += v2 + v3; q[i][1] += v2 * v2 + v3 * v3;
            }
        }
#pragma unroll
        for (int i = 0; i < 2; i++)
#pragma unroll
            for (int h = 0; h < 2; h++) {
                s[i][h] += __shfl_xor_sync(0xFFFFFFFFu, s[i][h], 1);
                s[i][h] += __shfl_xor_sync(0xFFFFFFFFu, s[i][h], 2);
                q[i][h] += __shfl_xor_sync(0xFFFFFFFFu, q[i][h], 1);
                q[i][h] += __shfl_xor_sync(0xFFFFFFFFu, q[i][h], 2);
            }
        if (qt == 0) {
#pragma unroll
            for (int i = 0; i < 2; i++)
#pragma unroll
                for (int h = 0; h < 2; h++) {
                    int lr = mW + i * 16 + g + h * 8;
                    sRedP[lr * 2 + wx]       = s[i][h];
                    sRedP[256 + lr * 2 + wx] = q[i][h];
                }
        }
        __syncthreads();
#pragma unroll
        for (int i = 0; i < 2; i++)
#pragma unroll
            for (int h = 0; h < 2; h++) {
                int lr = mW + i * 16 + g + h * 8;
                int gr = rowBase + lr;
                float ts = sRedP[lr * 2] + sRedP[lr * 2 + 1];
                float tq = sRedP[256 + lr * 2] + sRedP[256 + lr * 2 + 1];
                float mu = ts * (1.f / 128.f);
                float var = tq * (1.f / 128.f) - mu * mu;
                float rr = rsqrtf(var + 1e-5f);
                if (gr < M) {
#pragma unroll
                    for (int j = 0; j < 8; j++) {
                        int colL = nW + j * 8 + qt * 2;
                        float2 o;
                        o.x = (c[i][j][h * 2]     - mu) * rr * lng[colL]     + lnb[colL];
                        o.y = (c[i][j][h * 2 + 1] - mu) * rr * lng[colL + 1] + lnb[colL + 1];
                        *(float2*)(C + (size_t)gr * ldc + colL) = o;
                        __half2 oh = __floats2half2_rn(o.x, o.y);
                        *(uint32_t*)(C16 + (size_t)gr * ldc + colL) = *(uint32_t*)&oh;
                    }
                }
            }
    } else {
#pragma unroll
        for (int i = 0; i < 2; i++) {
            int r1 = rowBase + mW + i * 16 + g, r2 = r1 + 8;
#pragma unroll
            for (int j = 0; j < 8; j++) {
                int col = colBase + nW + j * 8 + qt * 2;
                float o0 = c[i][j][0] * cs[j][0] + ct[j][0];
                float o1 = c[i][j][1] * cs[j][1] + ct[j][1];
                float o2 = c[i][j][2] * cs[j][0] + ct[j][0];
                float o3 = c[i][j][3] * cs[j][1] + ct[j][1];
                if (EPI >= 1) {
                    o0 = fmaxf(o0, 0.f); o1 = fmaxf(o1, 0.f);
                    o2 = fmaxf(o2, 0.f); o3 = fmaxf(o3, 0.f);
                }
                if (O16) {
                    if (r1 < M) { __half2 oh = __floats2half2_rn(o0, o1);
                        *(uint32_t*)(C16 + (size_t)r1 * ldc + col) = *(uint32_t*)&oh; }
                    if (r2 < M) { __half2 oh = __floats2half2_rn(o2, o3);
                        *(uint32_t*)(C16 + (size_t)r2 * ldc + col) = *(uint32_t*)&oh; }
                } else {
                    if (r1 < M) { float2 o; o.x = o0; o.y = o1; *(float2*)(C + (size_t)r1 * ldc + col) = o; }
                    if (r2 < M) { float2 o; o.x = o2; o.y = o3; *(float2*)(C + (size_t)r2 * ldc + col) = o; }
                }
            }
        }
    }
}

// ---------------- global mean pool ----------------
__global__ void k_pool_acc(const float* __restrict__ emb, const int* __restrict__ batch, int n) {
    int c = threadIdx.x;
    int base = blockIdx.x * 64;
    float acc = 0.f, cnt = 0.f;
    int cur = -1;
    for (int i = 0; i < 64; i++) {
        int nd = base + i;
        if (nd >= n) break;
        int g = batch[nd];
        if (g != cur) {
            if (cur >= 0) {
                atomicAdd(&g_gsum[cur * 128 + c], acc);
                if (c == 0) atomicAdd(&g_cnt[cur], cnt);
            }
            cur = g; acc = 0.f; cnt = 0.f;
        }
        acc += emb[(size_t)nd * 128 + c];
        cnt += 1.f;
    }
    if (cur >= 0) {
        atomicAdd(&g_gsum[cur * 128 + c], acc);
        if (c == 0) atomicAdd(&g_cnt[cur], cnt);
    }
}
__global__ void k_pool_fin(float* __restrict__ out, int b) {
    int i = blockIdx.x * blockDim.x + threadIdx.x;
    if (i >= b * 128) return;
    out[i] = g_gsum[i] / fmaxf(g_cnt[i >> 7], 1.f);
}

// ---------------- launch ----------------
extern "C" void kernel_launch(void* const* d_in, const int* in_sizes, int n_in,
                              void* d_out, int out_size) {
    const float* x      = (const float*)d_in[0];
    const int*   ei     = (const int*)d_in[1];
    const float* ea     = (const float*)d_in[2];
    const int*   batch  = (const int*)d_in[3];
    const float* in_W   = (const float*)d_in[4];
    const float* in_b   = (const float*)d_in[5];
    const float* edge_W = (const float*)d_in[6];
    const float* edge_b = (const float*)d_in[7];
    const float* mlp_W1 = (const float*)d_in[8];
    const float* mlp_b1 = (const float*)d_in[9];
    const float* bn1_g  = (const float*)d_in[10];
    const float* bn1_b  = (const float*)d_in[11];
    const float* bn1_rm = (const float*)d_in[12];
    const float* bn1_rv = (const float*)d_in[13];
    const float* mlp_W2 = (const float*)d_in[14];
    const float* mlp_b2 = (const float*)d_in[15];
    const float* bn2_g  = (const float*)d_in[16];
    const float* bn2_b  = (const float*)d_in[17];
    const float* bn2_rm = (const float*)d_in[18];
    const float* bn2_rv = (const float*)d_in[19];
    const float* eps    = (const float*)d_in[20];
    const float* ln_g   = (const float*)d_in[21];
    const float* ln_b   = (const float*)d_in[22];
    const float* out_W1 = (const float*)d_in[23];
    const float* out_b1 = (const float*)d_in[24];
    const float* out_W2 = (const float*)d_in[25];
    const float* out_b2 = (const float*)d_in[26];

    int N = in_sizes[0] / 12;
    int E = in_sizes[2] / 3;
    int B = out_size / 128 - N;
    const int* src = ei;
    const int* dst = ei + E;
    float* node_emb  = (float*)d_out;
    float* graph_emb = node_emb + (size_t)N * 128;

    float *p_hcat;
    __half *p_wh, *p_wl, *p_hh, *p_z16, *p_t16, *p_o16;
    cudaGetSymbolAddress((void**)&p_hcat, g_hcat);
    cudaGetSymbolAddress((void**)&p_hh,   g_hh);
    cudaGetSymbolAddress((void**)&p_z16,  g_z16);
    cudaGetSymbolAddress((void**)&p_t16,  g_t16);
    cudaGetSymbolAddress((void**)&p_o16,  g_o16);
    cudaGetSymbolAddress((void**)&p_wh,   g_wth);
    cudaGetSymbolAddress((void**)&p_wl,   g_wtl);

    cudaFuncSetAttribute(k_mma<0, false>, cudaFuncAttributeMaxDynamicSharedMemorySize, SMEM_MMA);
    cudaFuncSetAttribute(k_mma<1, true>,  cudaFuncAttributeMaxDynamicSharedMemorySize, SMEM_MMA);
    cudaFuncSetAttribute(k_mma<2, true>,  cudaFuncAttributeMaxDynamicSharedMemorySize, SMEM_MMA);
    cudaFuncSetAttribute(k_mma<3, false>, cudaFuncAttributeMaxDynamicSharedMemorySize, SMEM_MMA);

    // fused init: prep + zero + in_proj (one launch)
    int gInit = (N + 1) / 2;
    if (gInit < 1089) gInit = 1089;
    k_init<<<gInit, 256>>>(x, in_W, in_b, mlp_W1, mlp_W2, out_W1, out_W2, N, B);

    k_count<<<(E + 255) / 256, 256>>>(dst, ea, E);
    int nb = (N + 511) / 512;
    k_scan1<<<nb, 512>>>(N);
    k_scan2<<<1, 256>>>(nb);
    k_scan3<<<(N + 255) / 256, 256>>>(N, E);
    k_scatter<<<(E + 255) / 256, 256>>>(src, dst, E);

    int gridM = (N + 127) / 128;
    for (int l = 0; l < 3; l++) {
        k_aggregate<<<(N * 32 + 255) / 256, 256>>>(edge_W + l * 384, edge_b + l * 128, eps, l, N);
        dim3 g1(2, gridM);
        k_mma<2, true><<<g1, 256, SMEM_MMA>>>(p_z16, 128, p_wh + l * 32768, p_wl + l * 32768, 128,
                              nullptr, p_t16, 256, N,
                              mlp_b1 + l * 256, bn1_g + l * 256, bn1_b + l * 256,
                              bn1_rm + l * 256, bn1_rv + l * 256,
                              nullptr, 0, nullptr, nullptr);
        dim3 g2(1, gridM);
        k_mma<3, false><<<g2, 256, SMEM_MMA>>>(p_t16, 256, p_wh + 98304 + l * 32768, p_wl + 98304 + l * 32768, 256,
                              p_hcat + (l + 1) * 128, p_hh + (l + 1) * 128, 512, N,
                              mlp_b2 + l * 128, bn2_g + l * 128, bn2_b + l * 128,
                              bn2_rm + l * 128, bn2_rv + l * 128,
                              p_hcat + l * 128, 512, ln_g + l * 128, ln_b + l * 128);
    }

    dim3 go(1, gridM);
    k_mma<1, true><<<go, 256, SMEM_MMA>>>(p_hh, 512, p_wh + 196608, p_wl + 196608, 512,
                          nullptr, p_o16, 128, N,
                          out_b1, nullptr, nullptr, nullptr, nullptr,
                          nullptr, 0, nullptr, nullptr);
    k_mma<0, false><<<go, 256, SMEM_MMA>>>(p_o16, 128, p_wh + 262144, p_wl + 262144, 128,
                          node_emb, nullptr, 128, N,
                          out_b2, nullptr, nullptr, nullptr, nullptr,
                          nullptr, 0, nullptr, nullptr);

    k_pool_acc<<<(N + 63) / 64, 128>>>(node_emb, batch, N);
    k_pool_fin<<<(B * 128 + 255) / 256, 256>>>(graph_emb, B);
}